// round 17
// baseline (speedup 1.0000x reference)
#include <cuda_runtime.h>
#include <cuda_fp16.h>
#include <mma.h>
#include <cstdint>

using namespace nvcuda;

#define N_NODES 100000
#define N_EDGES 1000000
#define D 64
#define NEG_SLOPE 0.01f

#define LDA 72   // half leading dim for A/B tiles
#define LDC 68   // float leading dim for C tile
#define ESRC_CAP (N_EDGES + 3 * N_NODES + 64)   // padded CSR capacity

// ---------------- scratch (no allocations allowed) ----------------
__device__ int   g_degOi[N_NODES];
__device__ int   g_degIi[N_NODES];
__device__ float g_oisq [N_NODES];
__device__ float g_iisq [N_NODES];
__device__ int   g_rowptr[N_NODES];       // padded CSR row start
__device__ int2  g_rows [N_NODES];        // {padded start, n4 = ceil(deg/4)}
__device__ int   g_rankE[N_EDGES];        // intra-node rank of each edge
__device__ int   g_total;                 // global row-offset cursor
__device__ __align__(16) int g_esrc[ESRC_CAP];   // CSR column (src), padded rows
__device__ __align__(16) half2 g_xh [((size_t)N_NODES + 1) * 32]; // x*oisq (+zero row)
__device__ __align__(16) half2 g_h1h[((size_t)N_NODES + 1) * 32]; // h1*oisq (+zero row)
__device__ __align__(16) half  g_W1h[D * D];
__device__ __align__(16) half  g_W2h[D * D];

// ------- degree histogram + rank capture (1 edge/thread) --------------------
// counters zero on entry: BSS-zero first call, re-zeroed by k_alloc after.
__global__ void k_deg(const int* __restrict__ src, const int* __restrict__ dst) {
    int e = blockIdx.x * blockDim.x + threadIdx.x;
    if (e >= N_EDGES) return;
    atomicAdd(&g_degOi[src[e]], 1);                    // no-return -> RED
    g_rankE[e] = atomicAdd(&g_degIi[dst[e]], 1);       // rank within dst row
}

// ------- padded row allocation + norms + pad fill; zero counters ------------
__global__ void k_alloc() {
    int i = blockIdx.x * blockDim.x + threadIdx.x;
    if (i >= N_NODES) return;
    int di = g_degIi[i];
    int dO = g_degOi[i];
    int padded = (di + 3) & ~3;
    int row = atomicAdd(&g_total, padded);   // grouping only; order irrelevant
    g_rowptr[i] = row;
    g_rows[i] = make_int2(row, padded >> 2);
    g_oisq[i] = rsqrtf((float)max(dO, 1));
    g_iisq[i] = rsqrtf((float)max(di, 1));
    for (int p = di; p < padded; p++) g_esrc[row + p] = N_NODES;  // dummy zero row
    g_degOi[i] = 0;                          // reset for next replay
    g_degIi[i] = 0;
}

// -- fused: CSR fill (no atomics) + x->fp16 convert + W->fp16; reset total ----
__global__ void k_convfill(const float* __restrict__ x,
                           const float* __restrict__ W1,
                           const float* __restrict__ W2,
                           const int* __restrict__ src,
                           const int* __restrict__ dst) {
    int t = blockIdx.x * blockDim.x + threadIdx.x;
    if (t == 0) g_total = 0;
    if (t < D * D)          g_W1h[t] = __float2half(W1[t]);
    else if (t < 2 * D * D) g_W2h[t - D * D] = __float2half(W2[t - D * D]);

    if (t < N_EDGES) {                       // CSR fill: rank precomputed
        int pos = __ldg(&g_rowptr[dst[t]]) + g_rankE[t];
        pos = min(pos, ESRC_CAP - 1);        // provable no-op; OOB guard
        g_esrc[pos] = src[t];
    }
    if (t < N_NODES * (D / 4)) {             // convert 1 float4 -> 2 half2
        int node = t >> 4;                   // 16 float4 per row
        float sc = g_oisq[node];
        float4 v = __ldg((const float4*)x + t);
        g_xh[t * 2 + 0] = __floats2half2_rn(v.x * sc, v.y * sc);
        g_xh[t * 2 + 1] = __floats2half2_rn(v.z * sc, v.w * sc);
    }
}

// =====================================================================
// Fused layers: fp16 gather (8 lanes/node, 4 nodes/warp), padded rows,
// 3-level HADD2 tree -> single fp32 acc -> half smem -> wmma (16 warps)
// Block: 512 threads, 64 nodes.
// =====================================================================

// acc += float((a+b)+(c+d)); two fp16 rounding levels on the 4-way sum
__device__ __forceinline__ void tree_acc(uint4 a, uint4 b, uint4 c, uint4 d,
                                         float2 acc[4]) {
    const half2* ha = (const half2*)&a;
    const half2* hb = (const half2*)&b;
    const half2* hc = (const half2*)&c;
    const half2* hd = (const half2*)&d;
#pragma unroll
    for (int j = 0; j < 4; j++) {
        half2 t = __hadd2(__hadd2(ha[j], hb[j]), __hadd2(hc[j], hd[j]));
        float2 f = __half22float2(t);
        acc[j].x += f.x; acc[j].y += f.y;
    }
}

// lane l (0..7) of a node-group covers feats [8l, 8l+8) = one uint4
__device__ __forceinline__ void group_aggregate(const uint4* __restrict__ feat,
                                                int node, int l,
                                                float2 acc[4]) {
    int2 rd = g_rows[node];
    int start = rd.x, n4 = rd.y;
    if (n4 == 0) return;
    const int4* ip = (const int4*)(g_esrc + start);   // 16B-aligned (padded rows)
    int4 idx = __ldg(ip);
    for (int k = 1; ; k++) {
        int4 cur = idx;
        if (k < n4) idx = __ldg(ip + k);              // prefetch next 4 indices
        uint4 v0 = __ldg(feat + (size_t)cur.x * 8 + l);
        uint4 v1 = __ldg(feat + (size_t)cur.y * 8 + l);
        uint4 v2 = __ldg(feat + (size_t)cur.z * 8 + l);
        uint4 v3 = __ldg(feat + (size_t)cur.w * 8 + l);
        tree_acc(v0, v1, v2, v3, acc);                // 3-level fp16 tree
        if (k >= n4) break;
    }
}

// aggregate block's 64 nodes -> half tile sA[64][LDA] (scaled by iisq)
__device__ __forceinline__ void aggregate_phase(const uint4* __restrict__ feat,
                                                int base, int tid, half* sA) {
    int g = tid >> 3, l = tid & 7;          // 64 groups x 8 lanes
    int gn = base + g;
    float2 acc[4] = {{0,0},{0,0},{0,0},{0,0}};
    if (gn < N_NODES) {
        group_aggregate(feat, gn, l, acc);
        float fi = g_iisq[gn];
#pragma unroll
        for (int j = 0; j < 4; j++) { acc[j].x *= fi; acc[j].y *= fi; }
    }
    half2 h[4];
#pragma unroll
    for (int j = 0; j < 4; j++) h[j] = __floats2half2_rn(acc[j].x, acc[j].y);
    *(uint4*)&sA[g * LDA + 8 * l] = *(uint4*)h;
}

// 16 warps, one 16x16 tile each: sC = sA @ sB
__device__ __forceinline__ void wmma_gemm(const half* sA, const half* sB,
                                          float* sC, int tid) {
    int w = tid >> 5;                        // 0..15
    int mi = w >> 2, ni = w & 3;
    wmma::fragment<wmma::accumulator, 16, 16, 16, float> c;
    wmma::fill_fragment(c, 0.f);
#pragma unroll
    for (int kk = 0; kk < 4; kk++) {
        wmma::fragment<wmma::matrix_a, 16, 16, 16, half, wmma::row_major> a;
        wmma::fragment<wmma::matrix_b, 16, 16, 16, half, wmma::row_major> bf;
        wmma::load_matrix_sync(a, sA + mi * 16 * LDA + kk * 16, LDA);
        wmma::load_matrix_sync(bf, sB + kk * 16 * LDA + ni * 16, LDA);
        wmma::mma_sync(c, a, bf, c);
    }
    wmma::store_matrix_sync(sC + mi * 16 * LDC + ni * 16, c, LDC,
                            wmma::mem_row_major);
}

// Layer 1
__global__ void __launch_bounds__(512, 3) k_layer1(const float* __restrict__ b) {
    __shared__ __align__(16) half  sA[64 * LDA];
    __shared__ __align__(16) half  sB[64 * LDA];
    __shared__ __align__(16) float sC[64 * LDC];
    __shared__ float sBias[D];
    int tid = threadIdx.x;
    int base = blockIdx.x * 64;

    for (int i = tid; i < D * D; i += 512)
        sB[(i >> 6) * LDA + (i & 63)] = g_W1h[i];
    if (tid < D) sBias[tid] = b[tid];

    aggregate_phase((const uint4*)g_xh, base, tid, sA);
    __syncthreads();

    wmma_gemm(sA, sB, sC, tid);
    __syncthreads();

    // epilogue: bias + lrelu + *oisq -> fp16 global; 8 cols (1 uint4)/thread
    int g = tid >> 3, q = tid & 7;
    int on = base + g;
    if (on < N_NODES) {
        float sc = __ldg(&g_oisq[on]);
        half2 hv[4];
#pragma unroll
        for (int j = 0; j < 4; j++) {
            int c0 = q * 8 + 2 * j;
            float y0 = sC[g * LDC + c0]     + sBias[c0];
            float y1 = sC[g * LDC + c0 + 1] + sBias[c0 + 1];
            y0 = (y0 > 0.f) ? y0 : NEG_SLOPE * y0;
            y1 = (y1 > 0.f) ? y1 : NEG_SLOPE * y1;
            hv[j] = __floats2half2_rn(y0 * sc, y1 * sc);
        }
        ((uint4*)&g_h1h[(size_t)on * 32])[q] = *(uint4*)hv;
    }
}

// Layer 2 + classifier
__global__ void __launch_bounds__(512, 3) k_layer2(
    const float* __restrict__ b2,
    const float* __restrict__ Wc, const float* __restrict__ bc,
    float* __restrict__ out)
{
    __shared__ __align__(16) half  sA[64 * LDA];
    __shared__ __align__(16) half  sB[64 * LDA];
    __shared__ __align__(16) float sC[64 * LDC];
    __shared__ float sBias[D];
    __shared__ float sWc[D * 2];
    int tid = threadIdx.x;
    int base = blockIdx.x * 64;

    for (int i = tid; i < D * D; i += 512)
        sB[(i >> 6) * LDA + (i & 63)] = g_W2h[i];
    if (tid < D) sBias[tid] = b2[tid];
    if (tid >= 64 && tid < 64 + D * 2) sWc[tid - 64] = Wc[tid - 64];

    aggregate_phase((const uint4*)g_h1h, base, tid, sA);
    __syncthreads();

    wmma_gemm(sA, sB, sC, tid);
    __syncthreads();

    // epilogue: bias + lrelu, in-place in sC (same thread reads/writes)
    int g = tid >> 3, q = tid & 7;
#pragma unroll
    for (int j = 0; j < 8; j++) {
        int c0 = q * 8 + j;
        float y = sC[g * LDC + c0] + sBias[c0];
        y = (y > 0.f) ? y : NEG_SLOPE * y;
        sC[g * LDC + c0] = y;
    }
    __syncthreads();

    // classifier: out[n][c] = bc[c] + sum_k h2[n][k] * Wc[k][c]
    if (tid < 128) {
        int n = tid >> 1, c = tid & 1;
        int on = base + n;
        if (on < N_NODES) {
            float s = bc[c];
#pragma unroll
            for (int k = 0; k < D; k++) s += sC[n * LDC + k] * sWc[k * 2 + c];
            out[(size_t)on * 2 + c] = s;
        }
    }
}

// ---------------- launch ----------------
extern "C" void kernel_launch(void* const* d_in, const int* in_sizes, int n_in,
                              void* d_out, int out_size) {
    const float* x   = (const float*)d_in[0];
    const int*   src = (const int*)  d_in[1];
    const int*   dst = (const int*)  d_in[2];
    const float* W1  = (const float*)d_in[3];
    const float* b1  = (const float*)d_in[4];
    const float* W2  = (const float*)d_in[5];
    const float* b2  = (const float*)d_in[6];
    const float* Wc  = (const float*)d_in[7];
    const float* bc  = (const float*)d_in[8];
    float* out = (float*)d_out;

    k_deg     <<<(N_EDGES + 255) / 256, 256>>>(src, dst);
    k_alloc   <<<(N_NODES + 255) / 256, 256>>>();
    k_convfill<<<(N_NODES * (D / 4) + 255) / 256, 256>>>(x, W1, W2, src, dst);

    k_layer1<<<(N_NODES + 63) / 64, 512>>>(b1);
    k_layer2<<<(N_NODES + 63) / 64, 512>>>(b2, Wc, bc, out);
}